// round 4
// baseline (speedup 1.0000x reference)
#include <cuda_runtime.h>
#include <cuda_bf16.h>

#define B_    32
#define H_    64
#define KVH_  8
#define D_    128
#define HID_  8192
#define CL_   1024
#define SP_   511
#define NTOT  10240

// ---------------- scratch ----------------
__device__ float    g_qkv[B_ * NTOT];     // fp32 qkv [b][n]
__device__ unsigned g_xhi[B_ * 4096];     // x hi bf16x2 [b][k/2]
__device__ unsigned g_xlo[B_ * 4096];
__device__ unsigned g_ahi[B_ * 4096];     // attn out hi bf16x2 [b][k/2]
__device__ unsigned g_alo[B_ * 4096];

// smem byte offsets (48 KB total)
#define SM_WHI 0
#define SM_WLO 16384
#define SM_BHI 32768
#define SM_BLO 40960
#define SM_TOT 49152

// ---------------- helpers ----------------
__device__ __forceinline__ void split2(float f0, float f1, unsigned& hi, unsigned& lo) {
    __nv_bfloat162 h = __floats2bfloat162_rn(f0, f1);
    unsigned hb = *reinterpret_cast<unsigned*>(&h);
    float h0 = __uint_as_float(hb << 16);
    float h1 = __uint_as_float(hb & 0xffff0000u);
    __nv_bfloat162 l = __floats2bfloat162_rn(f0 - h0, f1 - h1);
    hi = hb;
    lo = *reinterpret_cast<unsigned*>(&l);
}

__device__ __forceinline__ void ldsm4(unsigned& r0, unsigned& r1, unsigned& r2,
                                      unsigned& r3, unsigned addr) {
    asm volatile("ldmatrix.sync.aligned.m8n8.x4.shared.b16 {%0,%1,%2,%3}, [%4];"
                 : "=r"(r0), "=r"(r1), "=r"(r2), "=r"(r3) : "r"(addr));
}

__device__ __forceinline__ void mma16816(float* c, const unsigned* a,
                                         unsigned b0, unsigned b1) {
    asm volatile(
        "mma.sync.aligned.m16n8k16.row.col.f32.bf16.bf16.f32 "
        "{%0,%1,%2,%3}, {%4,%5,%6,%7}, {%8,%9}, {%0,%1,%2,%3};"
        : "+f"(c[0]), "+f"(c[1]), "+f"(c[2]), "+f"(c[3])
        : "r"(a[0]), "r"(a[1]), "r"(a[2]), "r"(a[3]), "r"(b0), "r"(b1));
}

// ---------------- x -> bf16 hi/lo ----------------
__global__ void cvt_x(const float* __restrict__ x) {
    int t = blockIdx.x * blockDim.x + threadIdx.x;      // 131072 pairs
    float f0 = x[2 * t], f1 = x[2 * t + 1];
    unsigned h, l;
    split2(f0, f1, h, l);
    g_xhi[t] = h;
    g_xlo[t] = l;
}

// ---------------- HMMA GEMM ----------------
// D[m = W-row][n = batch] = sum_k W[m][k] * B[n][k], written as C[n][m].
// BM=64 rows/CTA, 4 warps (warp = 16 rows x 32 batch), K=8192 chunked by 128.
// 3 bf16 passes: Whi*Bhi + Wlo*Bhi + Whi*Blo, fp32 accumulate.
__global__ __launch_bounds__(128)
void gemm_mma(int bsel,
              const float* __restrict__ W0, const float* __restrict__ W1,
              const float* __restrict__ W2,
              int nb1, int nb2,
              int csel, float* __restrict__ Cext, int ldc)
{
    extern __shared__ char smem[];
    unsigned sb = (unsigned)__cvta_generic_to_shared(smem);
    int tid = threadIdx.x, lane = tid & 31, wid = tid >> 5;

    int n0 = blockIdx.x * 64;
    const float* W; int wrow;
    if (n0 < nb1)      { W = W0; wrow = n0; }
    else if (n0 < nb2) { W = W1; wrow = n0 - nb1; }
    else               { W = W2; wrow = n0 - nb2; }

    const unsigned* __restrict__ Bh = bsel ? g_ahi : g_xhi;
    const unsigned* __restrict__ Bl = bsel ? g_alo : g_xlo;
    float* C = csel ? Cext : g_qkv;

    const float* wbase = W + (size_t)wrow * HID_;
    int sk = lane * 4;                       // k offset for W staging (0..124)

    // ldmatrix per-lane source descriptors
    int r0   = wid * 16;
    int arow = r0 + (lane & 7) + ((lane >> 3) & 1) * 8;
    int acs  = (lane >> 4) & 1;
    unsigned abase = (unsigned)(arow * 256);
    int arm  = arow & 7;
    int brow1 = (lane & 7) + ((lane >> 4) & 1) * 8;   // n rows 0..15
    int bcs   = (lane >> 3) & 1;
    int brow2 = brow1 + 16;                           // n rows 16..31

    float acc[4][4];
    #pragma unroll
    for (int i = 0; i < 4; ++i)
        #pragma unroll
        for (int j = 0; j < 4; ++j) acc[i][j] = 0.0f;

    for (int c = 0; c < 64; ++c) {
        int kc = c * 128;

        // ---- stage W (fp32 -> bf16 hi/lo, swizzled) ----
        #pragma unroll
        for (int i = 0; i < 16; ++i) {
            int row = wid + 4 * i;
            float4 w = *(const float4*)(wbase + (size_t)row * HID_ + kc + sk);
            unsigned h0, l0, h1, l1;
            split2(w.x, w.y, h0, l0);
            split2(w.z, w.w, h1, l1);
            unsigned seg = (unsigned)(sk >> 3);
            unsigned off = (unsigned)(row * 256) + ((seg ^ (unsigned)(row & 7)) << 4)
                         + ((unsigned)(sk & 4) << 1);
            *(uint2*)(smem + SM_WHI + off) = make_uint2(h0, h1);
            *(uint2*)(smem + SM_WLO + off) = make_uint2(l0, l1);
        }
        // ---- stage B (pre-split bf16 hi/lo from gmem, swizzled) ----
        #pragma unroll
        for (int i = 0; i < 4; ++i) {
            int idx = tid + 128 * i;               // 0..511
            int n = idx >> 4, s = idx & 15;
            size_t goff = (size_t)n * 4096 + (kc >> 1) + s * 4;
            uint4 vh = *(const uint4*)(Bh + goff);
            uint4 vl = *(const uint4*)(Bl + goff);
            unsigned off = (unsigned)(n * 256) + (((unsigned)s ^ (unsigned)(n & 7)) << 4);
            *(uint4*)(smem + SM_BHI + off) = vh;
            *(uint4*)(smem + SM_BLO + off) = vl;
        }
        __syncthreads();

        // ---- compute 8 k16 steps ----
        #pragma unroll
        for (int s = 0; s < 8; ++s) {
            unsigned aseg = (unsigned)(2 * s + acs);
            unsigned aoh = sb + SM_WHI + abase + ((aseg ^ (unsigned)arm) << 4);
            unsigned ah[4], al[4];
            ldsm4(ah[0], ah[1], ah[2], ah[3], aoh);
            ldsm4(al[0], al[1], al[2], al[3], aoh + (SM_WLO - SM_WHI));

            unsigned bseg = (unsigned)(2 * s + bcs);
            unsigned bo1 = sb + SM_BHI + (unsigned)(brow1 * 256)
                         + ((bseg ^ (unsigned)(brow1 & 7)) << 4);
            unsigned bo2 = sb + SM_BHI + (unsigned)(brow2 * 256)
                         + ((bseg ^ (unsigned)(brow2 & 7)) << 4);
            unsigned bh[8], bl[8];
            ldsm4(bh[0], bh[1], bh[2], bh[3], bo1);
            ldsm4(bh[4], bh[5], bh[6], bh[7], bo2);
            ldsm4(bl[0], bl[1], bl[2], bl[3], bo1 + (SM_BLO - SM_BHI));
            ldsm4(bl[4], bl[5], bl[6], bl[7], bo2 + (SM_BLO - SM_BHI));

            #pragma unroll
            for (int nt = 0; nt < 4; ++nt) {
                mma16816(acc[nt], ah, bh[2 * nt], bh[2 * nt + 1]);
                mma16816(acc[nt], al, bh[2 * nt], bh[2 * nt + 1]);
                mma16816(acc[nt], ah, bl[2 * nt], bl[2 * nt + 1]);
            }
        }
        __syncthreads();
    }

    // ---- epilogue: C[batch][wrow] plain stores ----
    int g = lane >> 2, t = lane & 3;
    int m = n0 + r0 + g;
    #pragma unroll
    for (int nt = 0; nt < 4; ++nt) {
        int col = nt * 8 + 2 * t;
        C[(size_t)col * ldc + m]           = acc[nt][0];
        C[(size_t)(col + 1) * ldc + m]     = acc[nt][1];
        C[(size_t)col * ldc + m + 8]       = acc[nt][2];
        C[(size_t)(col + 1) * ldc + m + 8] = acc[nt][3];
    }
}

// ---------------- RoPE (pairwise) ----------------
__global__ void rope_kernel(const float* __restrict__ rm) {
    int t = blockIdx.x * blockDim.x + threadIdx.x;   // 147456
    int p  = t & 63;
    int hr = t >> 6;
    int b  = hr / (H_ + KVH_);
    int hh = hr % (H_ + KVH_);
    float* ptr;
    if (hh < H_) ptr = g_qkv + (size_t)b * NTOT + hh * D_;
    else         ptr = g_qkv + (size_t)b * NTOT + HID_ + (hh - H_) * D_;
    float c = rm[(2 * p) * D_ + 2 * p];
    float s = rm[(2 * p + 1) * D_ + 2 * p];
    float e = ptr[2 * p], o = ptr[2 * p + 1];
    ptr[2 * p]     = fmaf(e, c,  o * s);
    ptr[2 * p + 1] = fmaf(o, c, -e * s);
}

// ---------------- attention ----------------
__global__ __launch_bounds__(256)
void attn_kernel(const float* __restrict__ cache_k,
                 const float* __restrict__ cache_v)
{
    int bidx = blockIdx.x;
    int b  = bidx >> 3;
    int kv = bidx & 7;
    int tid  = threadIdx.x;
    int r    = tid >> 5;
    int lane = tid & 31;

    __shared__ float sK[64][128];
    __shared__ float sS[8][512];

    const float scale = 0.0883883476483184405501055452631f;
    const float* qrow = g_qkv + (size_t)b * NTOT + (kv * 8 + r) * D_;
    float4 qv = *(const float4*)(qrow + lane * 4);
    qv.x *= scale; qv.y *= scale; qv.z *= scale; qv.w *= scale;

    const float* kb   = cache_k + ((size_t)(b * KVH_ + kv)) * CL_ * D_;
    const float* vb   = cache_v + ((size_t)(b * KVH_ + kv)) * CL_ * D_;
    const float* knew = g_qkv + (size_t)b * NTOT + HID_ + kv * D_;
    const float* vnew = g_qkv + (size_t)b * NTOT + HID_ + KVH_ * D_ + kv * D_;

    for (int c = 0; c < 8; ++c) {
        __syncthreads();
        #pragma unroll
        for (int i = 0; i < 8; ++i) {
            int v = tid + 256 * i;
            int j = v >> 5, dq = v & 31;
            int s = c * 64 + j;
            const float* src = (s == SP_) ? knew : (kb + (size_t)s * D_);
            *(float4*)&sK[j][dq * 4] = *(const float4*)(src + dq * 4);
        }
        __syncthreads();
        for (int j = 0; j < 64; ++j) {
            float4 k4 = *(const float4*)&sK[j][lane * 4];
            float p = qv.x * k4.x + qv.y * k4.y + qv.z * k4.z + qv.w * k4.w;
            #pragma unroll
            for (int o = 16; o; o >>= 1) p += __shfl_xor_sync(0xffffffffu, p, o);
            if (lane == 0) sS[r][c * 64 + j] = p;
        }
    }
    __syncthreads();

    float mx = -1e30f;
    #pragma unroll
    for (int i = 0; i < 16; ++i) mx = fmaxf(mx, sS[r][lane + 32 * i]);
    #pragma unroll
    for (int o = 16; o; o >>= 1) mx = fmaxf(mx, __shfl_xor_sync(0xffffffffu, mx, o));
    float sum = 0.0f;
    #pragma unroll
    for (int i = 0; i < 16; ++i) {
        float e = __expf(sS[r][lane + 32 * i] - mx);
        sS[r][lane + 32 * i] = e;
        sum += e;
    }
    #pragma unroll
    for (int o = 16; o; o >>= 1) sum += __shfl_xor_sync(0xffffffffu, sum, o);
    float inv = 1.0f / sum;
    #pragma unroll
    for (int i = 0; i < 16; ++i) sS[r][lane + 32 * i] *= inv;
    __syncthreads();

    float4 acc = make_float4(0.f, 0.f, 0.f, 0.f);
    for (int c = 0; c < 8; ++c) {
        __syncthreads();
        #pragma unroll
        for (int i = 0; i < 8; ++i) {
            int v = tid + 256 * i;
            int j = v >> 5, dq = v & 31;
            int s = c * 64 + j;
            const float* src = (s == SP_) ? vnew : (vb + (size_t)s * D_);
            *(float4*)&sK[j][dq * 4] = *(const float4*)(src + dq * 4);
        }
        __syncthreads();
        for (int j = 0; j < 64; ++j) {
            float pw = sS[r][c * 64 + j];
            float4 v4 = *(const float4*)&sK[j][lane * 4];
            acc.x = fmaf(pw, v4.x, acc.x);
            acc.y = fmaf(pw, v4.y, acc.y);
            acc.z = fmaf(pw, v4.z, acc.z);
            acc.w = fmaf(pw, v4.w, acc.w);
        }
    }
    // bf16 hi/lo split output for the wo GEMM (B operand layout [b][k/2])
    unsigned h0, l0, h1, l1;
    split2(acc.x, acc.y, h0, l0);
    split2(acc.z, acc.w, h1, l1);
    int h = kv * 8 + r;
    size_t wbase = (size_t)b * 4096 + h * 64 + lane * 2;
    g_ahi[wbase]     = h0;
    g_ahi[wbase + 1] = h1;
    g_alo[wbase]     = l0;
    g_alo[wbase + 1] = l1;
}

// ---------------- launcher ----------------
extern "C" void kernel_launch(void* const* d_in, const int* in_sizes, int n_in,
                              void* d_out, int out_size) {
    const float* x  = (const float*)d_in[0];
    const float* wq = (const float*)d_in[1];
    const float* wk = (const float*)d_in[2];
    const float* wv = (const float*)d_in[3];
    const float* wo = (const float*)d_in[4];
    const float* ck = (const float*)d_in[5];
    const float* cv = (const float*)d_in[6];
    const float* rm = (const float*)d_in[7];
    float* out = (float*)d_out;

    cudaFuncSetAttribute(gemm_mma, cudaFuncAttributeMaxDynamicSharedMemorySize, SM_TOT);

    // 1. split x into bf16 hi/lo
    cvt_x<<<512, 256>>>(x);

    // 2. fused QKV projection: 160 row-tiles of 64, full K, plain stores
    gemm_mma<<<160, 128, SM_TOT>>>(0, wq, wk, wv, 8192, 9216,
                                   0, nullptr, NTOT);

    // 3. RoPE on q and k
    rope_kernel<<<576, 256>>>(rm);

    // 4. attention (fp32 in, bf16 hi/lo out)
    attn_kernel<<<256, 256>>>(ck, cv);

    // 5. output projection: 128 row-tiles of 64, writes every d_out element once
    gemm_mma<<<128, 128, SM_TOT>>>(1, wo, wo, wo, 1 << 30, 1 << 30,
                                   1, out, HID_);
}

// round 5
// speedup vs baseline: 1.0001x; 1.0001x over previous
#include <cuda_runtime.h>
#include <cuda_bf16.h>

#define B_    32
#define H_    64
#define KVH_  8
#define D_    128
#define HID_  8192
#define CL_   1024
#define SP_   511
#define NTOT  10240

// ---------------- scratch ----------------
__device__ float    g_qkv[B_ * NTOT];     // fp32 qkv [b][n]
__device__ unsigned g_xhi[B_ * 4096];     // x hi bf16x2 [b][k/2]
__device__ unsigned g_xlo[B_ * 4096];
__device__ unsigned g_ahi[B_ * 4096];     // attn out hi bf16x2 [b][k/2]
__device__ unsigned g_alo[B_ * 4096];

// smem byte offsets (48 KB total)
#define SM_WHI 0
#define SM_WLO 16384
#define SM_BHI 32768
#define SM_BLO 40960
#define SM_TOT 49152

// ---------------- helpers ----------------
__device__ __forceinline__ void split2(float f0, float f1, unsigned& hi, unsigned& lo) {
    __nv_bfloat162 h = __floats2bfloat162_rn(f0, f1);
    unsigned hb = *reinterpret_cast<unsigned*>(&h);
    float h0 = __uint_as_float(hb << 16);
    float h1 = __uint_as_float(hb & 0xffff0000u);
    __nv_bfloat162 l = __floats2bfloat162_rn(f0 - h0, f1 - h1);
    hi = hb;
    lo = *reinterpret_cast<unsigned*>(&l);
}

__device__ __forceinline__ void ldsm4(unsigned& r0, unsigned& r1, unsigned& r2,
                                      unsigned& r3, unsigned addr) {
    asm volatile("ldmatrix.sync.aligned.m8n8.x4.shared.b16 {%0,%1,%2,%3}, [%4];"
                 : "=r"(r0), "=r"(r1), "=r"(r2), "=r"(r3) : "r"(addr));
}

__device__ __forceinline__ void mma16816(float* c, const unsigned* a,
                                         unsigned b0, unsigned b1) {
    asm volatile(
        "mma.sync.aligned.m16n8k16.row.col.f32.bf16.bf16.f32 "
        "{%0,%1,%2,%3}, {%4,%5,%6,%7}, {%8,%9}, {%0,%1,%2,%3};"
        : "+f"(c[0]), "+f"(c[1]), "+f"(c[2]), "+f"(c[3])
        : "r"(a[0]), "r"(a[1]), "r"(a[2]), "r"(a[3]), "r"(b0), "r"(b1));
}

// ---------------- x -> bf16 hi/lo ----------------
__global__ void cvt_x(const float* __restrict__ x) {
    int t = blockIdx.x * blockDim.x + threadIdx.x;      // 131072 pairs
    float f0 = x[2 * t], f1 = x[2 * t + 1];
    unsigned h, l;
    split2(f0, f1, h, l);
    g_xhi[t] = h;
    g_xlo[t] = l;
}

// ---------------- HMMA GEMM ----------------
// D[m = W-row][n = batch] = sum_k W[m][k] * B[n][k], written as C[n][m].
// BM=64 rows/CTA, 4 warps (warp = 16 rows x 32 batch), K=8192 chunked by 128.
// 3 bf16 passes: Whi*Bhi + Wlo*Bhi + Whi*Blo, fp32 accumulate.
__global__ __launch_bounds__(128)
void gemm_mma(int bsel,
              const float* __restrict__ W0, const float* __restrict__ W1,
              const float* __restrict__ W2,
              int nb1, int nb2,
              int csel, float* __restrict__ Cext, int ldc)
{
    extern __shared__ char smem[];
    unsigned sb = (unsigned)__cvta_generic_to_shared(smem);
    int tid = threadIdx.x, lane = tid & 31, wid = tid >> 5;

    int n0 = blockIdx.x * 64;
    const float* W; int wrow;
    if (n0 < nb1)      { W = W0; wrow = n0; }
    else if (n0 < nb2) { W = W1; wrow = n0 - nb1; }
    else               { W = W2; wrow = n0 - nb2; }

    const unsigned* __restrict__ Bh = bsel ? g_ahi : g_xhi;
    const unsigned* __restrict__ Bl = bsel ? g_alo : g_xlo;
    float* C = csel ? Cext : g_qkv;

    const float* wbase = W + (size_t)wrow * HID_;
    int sk = lane * 4;                       // k offset for W staging (0..124)

    // ldmatrix per-lane source descriptors
    int r0   = wid * 16;
    int arow = r0 + (lane & 7) + ((lane >> 3) & 1) * 8;
    int acs  = (lane >> 4) & 1;
    unsigned abase = (unsigned)(arow * 256);
    int arm  = arow & 7;
    int brow1 = (lane & 7) + ((lane >> 4) & 1) * 8;   // n rows 0..15
    int bcs   = (lane >> 3) & 1;
    int brow2 = brow1 + 16;                           // n rows 16..31

    float acc[4][4];
    #pragma unroll
    for (int i = 0; i < 4; ++i)
        #pragma unroll
        for (int j = 0; j < 4; ++j) acc[i][j] = 0.0f;

    for (int c = 0; c < 64; ++c) {
        int kc = c * 128;

        // ---- stage W (fp32 -> bf16 hi/lo, swizzled) ----
        #pragma unroll
        for (int i = 0; i < 16; ++i) {
            int row = wid + 4 * i;
            float4 w = *(const float4*)(wbase + (size_t)row * HID_ + kc + sk);
            unsigned h0, l0, h1, l1;
            split2(w.x, w.y, h0, l0);
            split2(w.z, w.w, h1, l1);
            unsigned seg = (unsigned)(sk >> 3);
            unsigned off = (unsigned)(row * 256) + ((seg ^ (unsigned)(row & 7)) << 4)
                         + ((unsigned)(sk & 4) << 1);
            *(uint2*)(smem + SM_WHI + off) = make_uint2(h0, h1);
            *(uint2*)(smem + SM_WLO + off) = make_uint2(l0, l1);
        }
        // ---- stage B (pre-split bf16 hi/lo from gmem, swizzled) ----
        #pragma unroll
        for (int i = 0; i < 4; ++i) {
            int idx = tid + 128 * i;               // 0..511
            int n = idx >> 4, s = idx & 15;
            size_t goff = (size_t)n * 4096 + (kc >> 1) + s * 4;
            uint4 vh = *(const uint4*)(Bh + goff);
            uint4 vl = *(const uint4*)(Bl + goff);
            unsigned off = (unsigned)(n * 256) + (((unsigned)s ^ (unsigned)(n & 7)) << 4);
            *(uint4*)(smem + SM_BHI + off) = vh;
            *(uint4*)(smem + SM_BLO + off) = vl;
        }
        __syncthreads();

        // ---- compute 8 k16 steps ----
        #pragma unroll
        for (int s = 0; s < 8; ++s) {
            unsigned aseg = (unsigned)(2 * s + acs);
            unsigned aoh = sb + SM_WHI + abase + ((aseg ^ (unsigned)arm) << 4);
            unsigned ah[4], al[4];
            ldsm4(ah[0], ah[1], ah[2], ah[3], aoh);
            ldsm4(al[0], al[1], al[2], al[3], aoh + (SM_WLO - SM_WHI));

            unsigned bseg = (unsigned)(2 * s + bcs);
            unsigned bo1 = sb + SM_BHI + (unsigned)(brow1 * 256)
                         + ((bseg ^ (unsigned)(brow1 & 7)) << 4);
            unsigned bo2 = sb + SM_BHI + (unsigned)(brow2 * 256)
                         + ((bseg ^ (unsigned)(brow2 & 7)) << 4);
            unsigned bh[8], bl[8];
            ldsm4(bh[0], bh[1], bh[2], bh[3], bo1);
            ldsm4(bh[4], bh[5], bh[6], bh[7], bo2);
            ldsm4(bl[0], bl[1], bl[2], bl[3], bo1 + (SM_BLO - SM_BHI));
            ldsm4(bl[4], bl[5], bl[6], bl[7], bo2 + (SM_BLO - SM_BHI));

            #pragma unroll
            for (int nt = 0; nt < 4; ++nt) {
                mma16816(acc[nt], ah, bh[2 * nt], bh[2 * nt + 1]);
                mma16816(acc[nt], al, bh[2 * nt], bh[2 * nt + 1]);
                mma16816(acc[nt], ah, bl[2 * nt], bl[2 * nt + 1]);
            }
        }
        __syncthreads();
    }

    // ---- epilogue: C[batch][wrow] plain stores ----
    int g = lane >> 2, t = lane & 3;
    int m = n0 + r0 + g;
    #pragma unroll
    for (int nt = 0; nt < 4; ++nt) {
        int col = nt * 8 + 2 * t;
        C[(size_t)col * ldc + m]           = acc[nt][0];
        C[(size_t)(col + 1) * ldc + m]     = acc[nt][1];
        C[(size_t)col * ldc + m + 8]       = acc[nt][2];
        C[(size_t)(col + 1) * ldc + m + 8] = acc[nt][3];
    }
}

// ---------------- RoPE (pairwise) ----------------
__global__ void rope_kernel(const float* __restrict__ rm) {
    int t = blockIdx.x * blockDim.x + threadIdx.x;   // 147456
    int p  = t & 63;
    int hr = t >> 6;
    int b  = hr / (H_ + KVH_);
    int hh = hr % (H_ + KVH_);
    float* ptr;
    if (hh < H_) ptr = g_qkv + (size_t)b * NTOT + hh * D_;
    else         ptr = g_qkv + (size_t)b * NTOT + HID_ + (hh - H_) * D_;
    float c = rm[(2 * p) * D_ + 2 * p];
    float s = rm[(2 * p + 1) * D_ + 2 * p];
    float e = ptr[2 * p], o = ptr[2 * p + 1];
    ptr[2 * p]     = fmaf(e, c,  o * s);
    ptr[2 * p + 1] = fmaf(o, c, -e * s);
}

// ---------------- attention ----------------
__global__ __launch_bounds__(256)
void attn_kernel(const float* __restrict__ cache_k,
                 const float* __restrict__ cache_v)
{
    int bidx = blockIdx.x;
    int b  = bidx >> 3;
    int kv = bidx & 7;
    int tid  = threadIdx.x;
    int r    = tid >> 5;
    int lane = tid & 31;

    __shared__ float sK[64][128];
    __shared__ float sS[8][512];

    const float scale = 0.0883883476483184405501055452631f;
    const float* qrow = g_qkv + (size_t)b * NTOT + (kv * 8 + r) * D_;
    float4 qv = *(const float4*)(qrow + lane * 4);
    qv.x *= scale; qv.y *= scale; qv.z *= scale; qv.w *= scale;

    const float* kb   = cache_k + ((size_t)(b * KVH_ + kv)) * CL_ * D_;
    const float* vb   = cache_v + ((size_t)(b * KVH_ + kv)) * CL_ * D_;
    const float* knew = g_qkv + (size_t)b * NTOT + HID_ + kv * D_;
    const float* vnew = g_qkv + (size_t)b * NTOT + HID_ + KVH_ * D_ + kv * D_;

    for (int c = 0; c < 8; ++c) {
        __syncthreads();
        #pragma unroll
        for (int i = 0; i < 8; ++i) {
            int v = tid + 256 * i;
            int j = v >> 5, dq = v & 31;
            int s = c * 64 + j;
            const float* src = (s == SP_) ? knew : (kb + (size_t)s * D_);
            *(float4*)&sK[j][dq * 4] = *(const float4*)(src + dq * 4);
        }
        __syncthreads();
        for (int j = 0; j < 64; ++j) {
            float4 k4 = *(const float4*)&sK[j][lane * 4];
            float p = qv.x * k4.x + qv.y * k4.y + qv.z * k4.z + qv.w * k4.w;
            #pragma unroll
            for (int o = 16; o; o >>= 1) p += __shfl_xor_sync(0xffffffffu, p, o);
            if (lane == 0) sS[r][c * 64 + j] = p;
        }
    }
    __syncthreads();

    float mx = -1e30f;
    #pragma unroll
    for (int i = 0; i < 16; ++i) mx = fmaxf(mx, sS[r][lane + 32 * i]);
    #pragma unroll
    for (int o = 16; o; o >>= 1) mx = fmaxf(mx, __shfl_xor_sync(0xffffffffu, mx, o));
    float sum = 0.0f;
    #pragma unroll
    for (int i = 0; i < 16; ++i) {
        float e = __expf(sS[r][lane + 32 * i] - mx);
        sS[r][lane + 32 * i] = e;
        sum += e;
    }
    #pragma unroll
    for (int o = 16; o; o >>= 1) sum += __shfl_xor_sync(0xffffffffu, sum, o);
    float inv = 1.0f / sum;
    #pragma unroll
    for (int i = 0; i < 16; ++i) sS[r][lane + 32 * i] *= inv;
    __syncthreads();

    float4 acc = make_float4(0.f, 0.f, 0.f, 0.f);
    for (int c = 0; c < 8; ++c) {
        __syncthreads();
        #pragma unroll
        for (int i = 0; i < 8; ++i) {
            int v = tid + 256 * i;
            int j = v >> 5, dq = v & 31;
            int s = c * 64 + j;
            const float* src = (s == SP_) ? vnew : (vb + (size_t)s * D_);
            *(float4*)&sK[j][dq * 4] = *(const float4*)(src + dq * 4);
        }
        __syncthreads();
        for (int j = 0; j < 64; ++j) {
            float pw = sS[r][c * 64 + j];
            float4 v4 = *(const float4*)&sK[j][lane * 4];
            acc.x = fmaf(pw, v4.x, acc.x);
            acc.y = fmaf(pw, v4.y, acc.y);
            acc.z = fmaf(pw, v4.z, acc.z);
            acc.w = fmaf(pw, v4.w, acc.w);
        }
    }
    // bf16 hi/lo split output for the wo GEMM (B operand layout [b][k/2])
    unsigned h0, l0, h1, l1;
    split2(acc.x, acc.y, h0, l0);
    split2(acc.z, acc.w, h1, l1);
    int h = kv * 8 + r;
    size_t wbase = (size_t)b * 4096 + h * 64 + lane * 2;
    g_ahi[wbase]     = h0;
    g_ahi[wbase + 1] = h1;
    g_alo[wbase]     = l0;
    g_alo[wbase + 1] = l1;
}

// ---------------- launcher ----------------
extern "C" void kernel_launch(void* const* d_in, const int* in_sizes, int n_in,
                              void* d_out, int out_size) {
    const float* x  = (const float*)d_in[0];
    const float* wq = (const float*)d_in[1];
    const float* wk = (const float*)d_in[2];
    const float* wv = (const float*)d_in[3];
    const float* wo = (const float*)d_in[4];
    const float* ck = (const float*)d_in[5];
    const float* cv = (const float*)d_in[6];
    const float* rm = (const float*)d_in[7];
    float* out = (float*)d_out;

    cudaFuncSetAttribute(gemm_mma, cudaFuncAttributeMaxDynamicSharedMemorySize, SM_TOT);

    // 1. split x into bf16 hi/lo
    cvt_x<<<512, 256>>>(x);

    // 2. fused QKV projection: 160 row-tiles of 64, full K, plain stores
    gemm_mma<<<160, 128, SM_TOT>>>(0, wq, wk, wv, 8192, 9216,
                                   0, nullptr, NTOT);

    // 3. RoPE on q and k
    rope_kernel<<<576, 256>>>(rm);

    // 4. attention (fp32 in, bf16 hi/lo out)
    attn_kernel<<<256, 256>>>(ck, cv);

    // 5. output projection: 128 row-tiles of 64, writes every d_out element once
    gemm_mma<<<128, 128, SM_TOT>>>(1, wo, wo, wo, 1 << 30, 1 << 30,
                                   1, out, HID_);
}